// round 2
// baseline (speedup 1.0000x reference)
#include <cuda_runtime.h>
#include <math.h>

#define T_  512
#define B_  64
#define IN_ 1024
#define H_  1024
#define BH  (B_*H_)            // 65536
#define TBH ((size_t)T_*BH)
#define NBLK 192

// Scratch (static __device__ arrays per harness rules)
__device__ float g_X0[T_*B_*H_];     // precomputed input GEMM + biases (128 MB)
__device__ float g_h0[2][BH];        // h0 ping-pong
__device__ float g_part0[8][BH];     // layer0 K-split partials
__device__ float g_part1[16][BH];    // layer1 K-split partials (K=2048 concat)

__device__ unsigned g_bar_count = 0;
__device__ unsigned g_bar_epoch = 0;

__device__ __forceinline__ void grid_barrier(){
    __syncthreads();
    if (threadIdx.x == 0){
        volatile unsigned* ep = &g_bar_epoch;
        unsigned e = *ep;                    // read BEFORE arriving (monotonic epoch)
        __threadfence();
        if (atomicAdd(&g_bar_count, 1u) == NBLK - 1u){
            g_bar_count = 0;
            __threadfence();
            atomicAdd(&g_bar_epoch, 1u);
        } else {
            while (*ep == e) { __nanosleep(32); }
        }
        __threadfence();
    }
    __syncthreads();
}

__device__ __forceinline__ void ffma2(unsigned long long &acc, unsigned long long a, unsigned long long b){
    asm("fma.rn.f32x2 %0, %1, %2, %0;" : "+l"(acc) : "l"(a), "l"(b));
}
__device__ __forceinline__ float lo32(unsigned long long u){ return __uint_as_float((unsigned)u); }
__device__ __forceinline__ float hi32(unsigned long long u){ return __uint_as_float((unsigned)(u>>32)); }

// Tile GEMM core: out[64 x 128] += A[64 x Ktot] * W[128 x Ktot]^T
// acc[i][c] packs rows (m0+2i, m0+2i+1) for col j0+c.
__device__ __forceinline__ void gemm_core(const float* __restrict__ A, int ldA,
                                          const float* __restrict__ W, int ldW,
                                          int Ktot, unsigned long long (&acc)[4][4])
{
    __shared__ __align__(16) float  sA[2][16][66];   // [k][row], padded
    __shared__ __align__(16) float2 sW[2][16][128];  // [k][j] duplicated {w,w}

    const int t    = threadIdx.x;
    const int arow = t >> 2, aq = t & 3;      // A staging: 64 rows x 4 quads
    const int wjj  = t >> 1, wh = t & 1;      // W staging: 128 rows x 2 halves
    const int lane = t & 31, warp = t >> 5;
    const int m0 = (warp >> 2)*32 + (lane >> 3)*8;   // 2 warp-rows x 4 bgroups
    const int j0 = (warp & 3)*32 + (lane & 7)*4;     // 4 warp-cols x 8 jgroups

    auto stage = [&](int buf, int kk){
        float4 v = *reinterpret_cast<const float4*>(A + arow*ldA + kk + 4*aq);
        sA[buf][4*aq+0][arow] = v.x;
        sA[buf][4*aq+1][arow] = v.y;
        sA[buf][4*aq+2][arow] = v.z;
        sA[buf][4*aq+3][arow] = v.w;
        const float* wp = W + wjj*ldW + kk + 8*wh;
        float4 w0 = *reinterpret_cast<const float4*>(wp);
        float4 w1 = *reinterpret_cast<const float4*>(wp + 4);
        sW[buf][8*wh+0][wjj] = make_float2(w0.x, w0.x);
        sW[buf][8*wh+1][wjj] = make_float2(w0.y, w0.y);
        sW[buf][8*wh+2][wjj] = make_float2(w0.z, w0.z);
        sW[buf][8*wh+3][wjj] = make_float2(w0.w, w0.w);
        sW[buf][8*wh+4][wjj] = make_float2(w1.x, w1.x);
        sW[buf][8*wh+5][wjj] = make_float2(w1.y, w1.y);
        sW[buf][8*wh+6][wjj] = make_float2(w1.z, w1.z);
        sW[buf][8*wh+7][wjj] = make_float2(w1.w, w1.w);
    };

    const int nIter = Ktot >> 4;
    stage(0, 0);
    __syncthreads();
    for (int it = 0; it < nIter; ++it){
        const int buf = it & 1;
        if (it + 1 < nIter) stage(buf ^ 1, (it + 1) << 4);
        #pragma unroll
        for (int kc = 0; kc < 16; ++kc){
            unsigned long long hp[4], wp2[4];
            #pragma unroll
            for (int i = 0; i < 4; ++i)
                hp[i] = *reinterpret_cast<const unsigned long long*>(&sA[buf][kc][m0 + 2*i]);
            #pragma unroll
            for (int c = 0; c < 4; ++c)
                wp2[c] = *reinterpret_cast<const unsigned long long*>(&sW[buf][kc][j0 + c]);
            #pragma unroll
            for (int i = 0; i < 4; ++i)
                #pragma unroll
                for (int c = 0; c < 4; ++c)
                    ffma2(acc[i][c], hp[i], wp2[c]);
        }
        __syncthreads();
    }
}

// ---- Phase 1: X0[i][j] = input[i][:] . W_ih0[j][:] + b_ih0[j] + b_hh0[j] ----
__global__ void __launch_bounds__(256) k_precompute(const float* __restrict__ input,
        const float* __restrict__ Wih0, const float* __restrict__ bih0, const float* __restrict__ bhh0)
{
    const int colt = blockIdx.x & 7;        // 8 col tiles of 128
    const int rowt = blockIdx.x >> 3;       // 512 row tiles of 64
    const float* A = input + (size_t)rowt * 64 * IN_;
    const float* W = Wih0 + (size_t)colt * 128 * IN_;

    unsigned long long acc[4][4] = {};
    gemm_core(A, IN_, W, IN_, IN_, acc);

    const int t = threadIdx.x, lane = t & 31, warp = t >> 5;
    const int m0 = (warp >> 2)*32 + (lane >> 3)*8;
    const int j0 = (warp & 3)*32 + (lane & 7)*4;
    const int jbase = colt*128 + j0;
    float bs[4];
    #pragma unroll
    for (int c = 0; c < 4; ++c) bs[c] = bih0[jbase+c] + bhh0[jbase+c];
    size_t rbase = ((size_t)rowt*64 + m0) * H_ + jbase;
    #pragma unroll
    for (int i = 0; i < 4; ++i){
        float4 vlo = make_float4(lo32(acc[i][0])+bs[0], lo32(acc[i][1])+bs[1],
                                 lo32(acc[i][2])+bs[2], lo32(acc[i][3])+bs[3]);
        float4 vhi = make_float4(hi32(acc[i][0])+bs[0], hi32(acc[i][1])+bs[1],
                                 hi32(acc[i][2])+bs[2], hi32(acc[i][3])+bs[3]);
        *reinterpret_cast<float4*>(&g_X0[rbase + (size_t)(2*i  )*H_]) = vlo;
        *reinterpret_cast<float4*>(&g_X0[rbase + (size_t)(2*i+1)*H_]) = vhi;
    }
}

// ---- Phase 2: persistent recurrence kernel. 192 blocks, all co-resident. ----
// Per step s: blocks 0..63 compute layer0 K-split partials (h0_{s-1} @ Whh0^T),
// blocks 64..191 compute layer1 partials for step s-1 (concat [h0_{s-1}|h1_{s-2}]).
// Then barrier, all blocks reduce+tanh, barrier.
__global__ void __launch_bounds__(256) k_persistent(
    const float* __restrict__ h0_in,        // h_0 [2,B,H]
    float* __restrict__ out,                // d_out
    const float* __restrict__ Whh0, const float* __restrict__ Wih1, const float* __restrict__ Whh1,
    const float* __restrict__ bih1, const float* __restrict__ bhh1)
{
    const int b = blockIdx.x;
    const int t = threadIdx.x;
    const float* h1_init = h0_in + BH;

    // init: h0_{-1} lives in buffer 1 (step 0 reads buffer (0+1)&1)
    for (int i = b*256 + t; i < BH; i += NBLK*256)
        g_h0[1][i] = h0_in[i];
    grid_barrier();

    for (int s = 0; s <= T_; ++s){
        const int pb = (s + 1) & 1;          // buffer holding h0_{s-1}

        // ---- GEMM phase ----
        const float* A = nullptr; const float* W = nullptr; float* P = nullptr;
        int colt = 0;
        bool active = false;
        if (b < 64){
            if (s < T_){
                colt = b & 7;
                const int kch = b >> 3;                     // 0..7
                A = g_h0[pb] + kch*128;
                W = Whh0 + (size_t)colt*128*H_ + kch*128;
                P = g_part0[kch];
                active = true;
            }
        } else {
            if (s >= 1){
                const int lb = b - 64;
                colt = lb & 7;
                const int kch = lb >> 3;                    // 0..15
                const int kg = kch * 128;
                if (kg < 1024){
                    A = g_h0[pb] + kg;
                    W = Wih1 + (size_t)colt*128*H_ + kg;
                } else {
                    const float* h1p = (s == 1) ? h1_init : (out + (size_t)(s-2)*BH);
                    A = h1p + (kg - 1024);
                    W = Whh1 + (size_t)colt*128*H_ + (kg - 1024);
                }
                P = g_part1[kch];
                active = true;
            }
        }

        if (active){
            unsigned long long acc[4][4] = {};
            gemm_core(A, H_, W, H_, 128, acc);
            const int lane = t & 31, warp = t >> 5;
            const int m0 = (warp >> 2)*32 + (lane >> 3)*8;
            const int j0 = (warp & 3)*32 + (lane & 7)*4;
            size_t base = (size_t)m0*H_ + colt*128 + j0;
            #pragma unroll
            for (int i = 0; i < 4; ++i){
                float4 vlo = make_float4(lo32(acc[i][0]), lo32(acc[i][1]), lo32(acc[i][2]), lo32(acc[i][3]));
                float4 vhi = make_float4(hi32(acc[i][0]), hi32(acc[i][1]), hi32(acc[i][2]), hi32(acc[i][3]));
                *reinterpret_cast<float4*>(&P[base + (size_t)(2*i  )*H_]) = vlo;
                *reinterpret_cast<float4*>(&P[base + (size_t)(2*i+1)*H_]) = vhi;
            }
        }
        grid_barrier();

        // ---- reduce + tanh phase ----
        {
            const bool L0 = (s < T_), L1 = (s >= 1);
            const int nA = L0 ? BH : 0;
            const int total = nA + (L1 ? BH : 0);
            for (int idx = b*256 + t; idx < total; idx += NBLK*256){
                if (idx < nA){
                    float v = g_X0[(size_t)s*BH + idx];
                    #pragma unroll
                    for (int p = 0; p < 8; ++p) v += g_part0[p][idx];
                    g_h0[s & 1][idx] = tanhf(v);
                } else {
                    const int e = idx - nA;
                    const int j = e & (H_ - 1);
                    float v = bih1[j] + bhh1[j];
                    #pragma unroll
                    for (int p = 0; p < 16; ++p) v += g_part1[p][e];
                    out[(size_t)(s-1)*BH + e] = tanhf(v);
                }
            }
        }
        grid_barrier();
    }

    // final h_n: h_n[0] = h0_{T-1}, h_n[1] = h1_{T-1} (already in out[T-1])
    for (int i = b*256 + t; i < BH; i += NBLK*256){
        out[TBH + i]      = g_h0[(T_-1) & 1][i];
        out[TBH + BH + i] = out[(size_t)(T_-1)*BH + i];
    }
}

extern "C" void kernel_launch(void* const* d_in, const int* in_sizes, int n_in,
                              void* d_out, int out_size)
{
    const float* input = (const float*)d_in[0];
    const float* h0in  = (const float*)d_in[1];   // [2, B, H]
    const float* Wih0  = (const float*)d_in[2];
    const float* bih0  = (const float*)d_in[3];
    const float* Whh0  = (const float*)d_in[4];
    const float* bhh0  = (const float*)d_in[5];
    const float* Wih1  = (const float*)d_in[6];
    const float* bih1  = (const float*)d_in[7];
    const float* Whh1  = (const float*)d_in[8];
    const float* bhh1  = (const float*)d_in[9];
    float* out = (float*)d_out;

    k_precompute<<<4096, 256>>>(input, Wih0, bih0, bhh0);
    k_persistent<<<NBLK, 256>>>(h0in, out, Whh0, Wih1, Whh1, bih1, bhh1);
}